// round 2
// baseline (speedup 1.0000x reference)
#include <cuda_runtime.h>
#include <cstdint>
#include <math.h>

// ---------------------------------------------------------------------------
// TransFuse network on GB300.
//   bridge_in[512,8000] = [relu(snp @ (W_sg^T*adj_sg) + b) | relu(gen @ (W_gp^T*adj_gp) + b)]
//   fuse[512,6000]      = [relu(bridge_in @ (W_br^T*adj_br) + b) | relu(pro @ (W_pp^T*adj_pp) + b)]
//   h1 = relu(fuse @ W_h1^T + b); h2 = relu(h1 @ W_h2^T + b); y = sigmoid(h2 @ W_out^T + b)
// Generic TF32 tensor-core GEMM:  C[m,n] = sum_k A[m,k] * (W[n,k] * adj[k,n])
// ---------------------------------------------------------------------------

#define BM 128
#define BN 64
#define BK 32
#define NTHREADS 256

// Scratch activations (allocation-free: __device__ globals)
__device__ float g_bridge[512 * 8000];
__device__ float g_fuse[512 * 6000];
__device__ float g_h1[512 * 1024];
__device__ float g_h2[512 * 256];

__device__ __forceinline__ uint32_t f2tf32(float f) {
    uint32_t r;
    asm("cvt.rna.tf32.f32 %0, %1;" : "=r"(r) : "f"(f));
    return r;
}

__device__ __forceinline__ void mma_tf32(float c[4], const uint32_t a[4], const uint32_t b[2]) {
    asm volatile(
        "mma.sync.aligned.m16n8k8.row.col.f32.tf32.tf32.f32 "
        "{%0,%1,%2,%3}, {%4,%5,%6,%7}, {%8,%9}, {%0,%1,%2,%3};\n"
        : "+f"(c[0]), "+f"(c[1]), "+f"(c[2]), "+f"(c[3])
        : "r"(a[0]), "r"(a[1]), "r"(a[2]), "r"(a[3]), "r"(b[0]), "r"(b[1]));
}

// C[m,n] = relu( sum_k A[m,k] * (W[n,k] * adjmask[k,n]) + bias[n] )
// A: [512, >=K] row-major stride ldA (fp32)
// W: [N, K] row-major stride ldW (fp32)
// adj: [K, N] row-major stride ldAdj (fp32 0/1 mask), may be nullptr
// out: [512, >=N] row-major stride ldOut (fp32)
__global__ __launch_bounds__(NTHREADS)
void gemm_masked_kernel(const float* __restrict__ A, int ldA,
                        const float* __restrict__ W, int ldW,
                        const float* __restrict__ adj, int ldAdj,
                        const float* __restrict__ bias,
                        float* __restrict__ out, int ldOut,
                        int N, int K)
{
    __shared__ uint32_t As[BM][BK + 1];   // tf32 bits of A tile   [m][k]
    __shared__ uint32_t Bs[BK][BN + 1];   // adj fp32 bits, then tf32 masked-W bits [k][n]

    const int tid  = threadIdx.x;
    const int warp = tid >> 5;
    const int lane = tid & 31;
    const int wm = (warp >> 1) * 32;      // 4 warps along M
    const int wn = (warp & 1) * 32;       // 2 warps along N
    const int bm0 = blockIdx.y * BM;
    const int bn0 = blockIdx.x * BN;

    float acc[2][4][4];
    #pragma unroll
    for (int mt = 0; mt < 2; ++mt)
        #pragma unroll
        for (int nt = 0; nt < 4; ++nt)
            #pragma unroll
            for (int i = 0; i < 4; ++i) acc[mt][nt][i] = 0.0f;

    const bool has_adj = (adj != nullptr);
    const int ktiles = (K + BK - 1) / BK;

    for (int kt = 0; kt < ktiles; ++kt) {
        const int k0 = kt * BK;

        // ---- load A tile: 128 rows x 8 float4 (K % 4 == 0 for all layers) ----
        #pragma unroll
        for (int i = 0; i < 4; ++i) {
            int idx = tid + i * NTHREADS;           // 0..1023
            int row = idx >> 3;
            int kg  = (idx & 7) * 4;
            int k = k0 + kg;
            float4 v = make_float4(0.f, 0.f, 0.f, 0.f);
            if (k < K)
                v = *reinterpret_cast<const float4*>(A + (size_t)(bm0 + row) * ldA + k);
            As[row][kg + 0] = f2tf32(v.x);
            As[row][kg + 1] = f2tf32(v.y);
            As[row][kg + 2] = f2tf32(v.z);
            As[row][kg + 3] = f2tf32(v.w);
        }

        // ---- phase 1: adj mask tile into Bs (as fp32 bits), coalesced along n ----
        if (has_adj) {
            #pragma unroll
            for (int i = 0; i < 2; ++i) {
                int idx = tid + i * NTHREADS;       // 0..511 : 32 k-rows x 16 n-float4s
                int kk = idx >> 4;
                int ng = (idx & 15) * 4;
                int k = k0 + kk, n = bn0 + ng;
                float4 v = make_float4(0.f, 0.f, 0.f, 0.f);
                if (k < K && n < N)
                    v = *reinterpret_cast<const float4*>(adj + (size_t)k * ldAdj + n);
                Bs[kk][ng + 0] = __float_as_uint(v.x);
                Bs[kk][ng + 1] = __float_as_uint(v.y);
                Bs[kk][ng + 2] = __float_as_uint(v.z);
                Bs[kk][ng + 3] = __float_as_uint(v.w);
            }
            __syncthreads();
        }

        // ---- phase 2: W tile (coalesced along k per n-row), fuse mask, write tf32 ----
        #pragma unroll
        for (int i = 0; i < 2; ++i) {
            int idx = tid + i * NTHREADS;           // 0..511 : 64 n-rows x 8 k-float4s
            int nl = idx >> 3;
            int kg = (idx & 7) * 4;
            int n = bn0 + nl, k = k0 + kg;
            float4 w = make_float4(0.f, 0.f, 0.f, 0.f);
            if (n < N && k < K)
                w = *reinterpret_cast<const float4*>(W + (size_t)n * ldW + k);
            #pragma unroll
            for (int j = 0; j < 4; ++j) {
                float wv = (&w.x)[j];
                float m = has_adj ? __uint_as_float(Bs[kg + j][nl]) : 1.0f;
                Bs[kg + j][nl] = f2tf32(wv * m);    // same thread reads & rewrites slot
            }
        }
        __syncthreads();

        // ---- tensor-core compute: 4 k-steps of m16n8k8 ----
        const int r = lane >> 2;
        const int c = lane & 3;
        #pragma unroll
        for (int ks = 0; ks < 4; ++ks) {
            const int kb = ks * 8;
            uint32_t af[2][4];
            uint32_t bf[4][2];
            #pragma unroll
            for (int mt = 0; mt < 2; ++mt) {
                int m0 = wm + mt * 16;
                af[mt][0] = As[m0 + r][kb + c];
                af[mt][1] = As[m0 + r + 8][kb + c];
                af[mt][2] = As[m0 + r][kb + c + 4];
                af[mt][3] = As[m0 + r + 8][kb + c + 4];
            }
            #pragma unroll
            for (int nt = 0; nt < 4; ++nt) {
                int n0 = wn + nt * 8 + r;
                bf[nt][0] = Bs[kb + c][n0];
                bf[nt][1] = Bs[kb + 4 + c][n0];
            }
            #pragma unroll
            for (int mt = 0; mt < 2; ++mt)
                #pragma unroll
                for (int nt = 0; nt < 4; ++nt)
                    mma_tf32(acc[mt][nt], af[mt], bf[nt]);
        }
        __syncthreads();  // protect shared tiles before next iteration's writes
    }

    // ---- epilogue: bias + relu, fp32 store ----
    const int r = lane >> 2;
    const int c = (lane & 3) * 2;
    #pragma unroll
    for (int mt = 0; mt < 2; ++mt) {
        #pragma unroll
        for (int nt = 0; nt < 4; ++nt) {
            int m = bm0 + wm + mt * 16 + r;
            int n = bn0 + wn + nt * 8 + c;
            float* cr = acc[mt][nt];
            if (n < N) {
                float v = cr[0] + bias[n];
                out[(size_t)m * ldOut + n] = v > 0.f ? v : 0.f;
                float v2 = cr[2] + bias[n];
                out[(size_t)(m + 8) * ldOut + n] = v2 > 0.f ? v2 : 0.f;
            }
            if (n + 1 < N) {
                float v = cr[1] + bias[n + 1];
                out[(size_t)m * ldOut + n + 1] = v > 0.f ? v : 0.f;
                float v2 = cr[3] + bias[n + 1];
                out[(size_t)(m + 8) * ldOut + n + 1] = v2 > 0.f ? v2 : 0.f;
            }
        }
    }
}

// y[b] = sigmoid( dot(h2[b,:], W_out[0,:]) + b_out ), K = 256, one warp per row
__global__ void head_kernel(const float* __restrict__ h2,
                            const float* __restrict__ W_out,
                            const float* __restrict__ b_out,
                            float* __restrict__ out)
{
    int b = blockIdx.x;
    int lane = threadIdx.x;
    float s = 0.f;
    #pragma unroll
    for (int k = lane; k < 256; k += 32)
        s += h2[b * 256 + k] * W_out[k];
    #pragma unroll
    for (int o = 16; o > 0; o >>= 1)
        s += __shfl_down_sync(0xFFFFFFFFu, s, o);
    if (lane == 0)
        out[b] = 1.0f / (1.0f + expf(-(s + b_out[0])));
}

static void launch_gemm(const float* A, int ldA, const float* W, int ldW,
                        const float* adj, int ldAdj, const float* bias,
                        float* out, int ldOut, int N, int K)
{
    dim3 grid((N + BN - 1) / BN, 512 / BM);
    gemm_masked_kernel<<<grid, NTHREADS>>>(A, ldA, W, ldW, adj, ldAdj, bias, out, ldOut, N, K);
}

extern "C" void kernel_launch(void* const* d_in, const int* in_sizes, int n_in,
                              void* d_out, int out_size)
{
    const float* in_mat  = (const float*)d_in[0];   // [512, 28000]
    const float* adj_sg  = (const float*)d_in[1];   // [20000, 5000]
    const float* adj_gp  = (const float*)d_in[2];   // [5000, 3000]
    const float* adj_br  = (const float*)d_in[3];   // [8000, 3000]
    const float* adj_pp  = (const float*)d_in[4];   // [3000, 3000]
    const float* W_sg    = (const float*)d_in[5];   // [5000, 20000]
    const float* b_sg    = (const float*)d_in[6];
    const float* W_gp    = (const float*)d_in[7];   // [3000, 5000]
    const float* b_gp    = (const float*)d_in[8];
    const float* W_br    = (const float*)d_in[9];   // [3000, 8000]
    const float* b_br    = (const float*)d_in[10];
    const float* W_pp    = (const float*)d_in[11];  // [3000, 3000]
    const float* b_pp    = (const float*)d_in[12];
    const float* W_h1    = (const float*)d_in[13];  // [1024, 6000]
    const float* b_h1    = (const float*)d_in[14];
    const float* W_h2    = (const float*)d_in[15];  // [256, 1024]
    const float* b_h2    = (const float*)d_in[16];
    const float* W_out   = (const float*)d_in[17];  // [1, 256]
    const float* b_out   = (const float*)d_in[18];
    float* out = (float*)d_out;                     // [512, 1]

    float *bridge, *fuse, *h1, *h2;
    cudaGetSymbolAddress((void**)&bridge, g_bridge);
    cudaGetSymbolAddress((void**)&fuse,   g_fuse);
    cudaGetSymbolAddress((void**)&h1,     g_h1);
    cudaGetSymbolAddress((void**)&h2,     g_h2);

    // snp layer: cols [8000, 28000) of in_mat
    launch_gemm(in_mat + 8000, 28000, W_sg, 20000, adj_sg, 5000, b_sg,
                bridge, 8000, 5000, 20000);
    // gene layer: cols [3000, 8000)
    launch_gemm(in_mat + 3000, 28000, W_gp, 5000, adj_gp, 3000, b_gp,
                bridge + 5000, 8000, 3000, 5000);
    // protein layer: cols [0, 3000) -> fuse[:, 3000:6000)
    launch_gemm(in_mat, 28000, W_pp, 3000, adj_pp, 3000, b_pp,
                fuse + 3000, 6000, 3000, 3000);
    // bridge layer: depends on the first two
    launch_gemm(bridge, 8000, W_br, 8000, adj_br, 3000, b_br,
                fuse, 6000, 3000, 8000);
    // dense h1 / h2
    launch_gemm(fuse, 6000, W_h1, 6000, nullptr, 0, b_h1, h1, 1024, 1024, 6000);
    launch_gemm(h1, 1024, W_h2, 1024, nullptr, 0, b_h2, h2, 256, 256, 1024);
    // sigmoid head
    head_kernel<<<512, 32>>>(h2, W_out, b_out, out);
}

// round 3
// speedup vs baseline: 1.9706x; 1.9706x over previous
#include <cuda_runtime.h>
#include <cstdint>
#include <math.h>

// ---------------------------------------------------------------------------
// TransFuse on GB300 — round 3.
// TF32 tensor-core GEMM, cp.async double-buffered pipeline, mask fused at
// fragment-load time, raw-fp32-bits-as-tf32 (no cvt).
//   C[m,n] = relu( sum_k A[m,k] * (W[n,k] * adj[k,n]) + bias[n] )
// ---------------------------------------------------------------------------

__device__ float g_bridge[512 * 8000];
__device__ float g_fuse[512 * 6000];
__device__ float g_h1[512 * 1024];
__device__ float g_h2[512 * 256];

#define AS_STR  36   // A/W smem row stride (floats): bank = 4r+c = lane, conflict-free
#define ADJ_STR 136  // adj smem row stride: bank = 8c+r, conflict-free

__device__ __forceinline__ void cp16(float* dst, const float* src, bool p) {
    uint32_t s = (uint32_t)__cvta_generic_to_shared(dst);
    int sz = p ? 16 : 0;
    asm volatile("cp.async.cg.shared.global [%0], [%1], 16, %2;\n"
                 :: "r"(s), "l"(src), "r"(sz));
}
__device__ __forceinline__ void cp_commit() {
    asm volatile("cp.async.commit_group;\n");
}
template <int N_>
__device__ __forceinline__ void cp_wait() {
    asm volatile("cp.async.wait_group %0;\n" :: "n"(N_));
}

__device__ __forceinline__ void mma_tf32(float c[4], const uint32_t a[4], const uint32_t b[2]) {
    asm volatile(
        "mma.sync.aligned.m16n8k8.row.col.f32.tf32.tf32.f32 "
        "{%0,%1,%2,%3}, {%4,%5,%6,%7}, {%8,%9}, {%0,%1,%2,%3};\n"
        : "+f"(c[0]), "+f"(c[1]), "+f"(c[2]), "+f"(c[3])
        : "r"(a[0]), "r"(a[1]), "r"(a[2]), "r"(a[3]), "r"(b[0]), "r"(b[1]));
}

// BM_ x BN_ CTA tile, BK=32, 256 threads, warp grid 2(m) x 4(n).
// Warp tile (BM_/2) x (BN_/4); MT = BM_/32 m16-tiles, NT = BN_/32 n8-tiles... (x2)
template <int BM_, int BN_, bool HAS_ADJ>
__global__ __launch_bounds__(256)
void gemm_tf32(const float* __restrict__ A, int ldA,
               const float* __restrict__ W, int ldW,
               const float* __restrict__ adj, int ldAdj,
               const float* __restrict__ bias,
               float* __restrict__ out, int ldOut,
               int N, int K)
{
    constexpr int MT = BM_ / 32;   // m16 tiles per warp
    constexpr int NT = BN_ / 32;   // n8 tiles per warp (warp covers NT*8 = BN_/4 cols)
    constexpr int A_SZ = BM_ * AS_STR;
    constexpr int W_SZ = BN_ * AS_STR;
    constexpr int ADJ_SZ = 32 * ADJ_STR;

    extern __shared__ float sm[];
    float* Asm[2] = { sm,               sm + A_SZ };
    float* Wsm[2] = { sm + 2*A_SZ,      sm + 2*A_SZ + W_SZ };
    float* Dsm[2] = { sm + 2*A_SZ + 2*W_SZ, sm + 2*A_SZ + 2*W_SZ + ADJ_SZ };

    const int tid  = threadIdx.x;
    const int warp = tid >> 5;
    const int lane = tid & 31;
    const int wm = (warp >> 2) * (BM_ / 2);
    const int wn = (warp & 3) * (BN_ / 4);
    const int bm0 = blockIdx.y * BM_;
    const int bn0 = blockIdx.x * BN_;
    const int r = lane >> 2;
    const int c = lane & 3;

    float acc[MT][NT][4];
    #pragma unroll
    for (int mt = 0; mt < MT; ++mt)
        #pragma unroll
        for (int nt = 0; nt < NT; ++nt)
            #pragma unroll
            for (int i = 0; i < 4; ++i) acc[mt][nt][i] = 0.0f;

    const int ktiles = (K + 31) >> 5;

    auto issue = [&](int kt, int buf) {
        const int k0 = kt * 32;
        #pragma unroll
        for (int i = 0; i < BM_ / 32; ++i) {
            int idx = tid + i * 256;
            int row = idx >> 3;
            int ck  = (idx & 7) * 4;
            cp16(Asm[buf] + row * AS_STR + ck,
                 A + (size_t)(bm0 + row) * ldA + k0 + ck,
                 (k0 + ck) < K);
        }
        #pragma unroll
        for (int i = 0; i < BN_ / 32; ++i) {
            int idx = tid + i * 256;
            int row = idx >> 3;
            int ck  = (idx & 7) * 4;
            cp16(Wsm[buf] + row * AS_STR + ck,
                 W + (size_t)(bn0 + row) * ldW + k0 + ck,
                 (bn0 + row) < N && (k0 + ck) < K);
        }
        if (HAS_ADJ) {
            #pragma unroll
            for (int i = 0; i < BN_ / 32; ++i) {
                int idx = tid + i * 256;
                int kk = idx / (BN_ / 4);
                int nn = (idx % (BN_ / 4)) * 4;
                cp16(Dsm[buf] + kk * ADJ_STR + nn,
                     adj + (size_t)(k0 + kk) * ldAdj + bn0 + nn,
                     (k0 + kk) < K && (bn0 + nn) < N);
            }
        }
        cp_commit();
    };

    issue(0, 0);

    for (int kt = 0; kt < ktiles; ++kt) {
        const int buf = kt & 1;
        if (kt + 1 < ktiles) {
            issue(kt + 1, buf ^ 1);
            cp_wait<1>();
        } else {
            cp_wait<0>();
        }
        __syncthreads();

        const float* As = Asm[buf];
        const float* Ws = Wsm[buf];
        const float* Ds = Dsm[buf];

        #pragma unroll
        for (int ks = 0; ks < 4; ++ks) {
            const int kb = ks * 8;
            uint32_t af[MT][4];
            #pragma unroll
            for (int mt = 0; mt < MT; ++mt) {
                const float* ap = As + (wm + mt * 16 + r) * AS_STR + kb + c;
                af[mt][0] = __float_as_uint(ap[0]);
                af[mt][1] = __float_as_uint(ap[8 * AS_STR]);
                af[mt][2] = __float_as_uint(ap[4]);
                af[mt][3] = __float_as_uint(ap[8 * AS_STR + 4]);
            }
            uint32_t bf[NT][2];
            #pragma unroll
            for (int nt = 0; nt < NT; ++nt) {
                const int n0 = wn + nt * 8 + r;
                float w0 = Ws[n0 * AS_STR + kb + c];
                float w1 = Ws[n0 * AS_STR + kb + 4 + c];
                if (HAS_ADJ) {
                    w0 *= Ds[(kb + c) * ADJ_STR + n0];
                    w1 *= Ds[(kb + 4 + c) * ADJ_STR + n0];
                }
                bf[nt][0] = __float_as_uint(w0);
                bf[nt][1] = __float_as_uint(w1);
            }
            #pragma unroll
            for (int mt = 0; mt < MT; ++mt)
                #pragma unroll
                for (int nt = 0; nt < NT; ++nt)
                    mma_tf32(acc[mt][nt], af[mt], bf[nt]);
        }
        __syncthreads();
    }

    // epilogue: bias + relu
    const int c2 = (lane & 3) * 2;
    #pragma unroll
    for (int mt = 0; mt < MT; ++mt) {
        #pragma unroll
        for (int nt = 0; nt < NT; ++nt) {
            int m = bm0 + wm + mt * 16 + r;
            int n = bn0 + wn + nt * 8 + c2;
            float* cr = acc[mt][nt];
            if (n < N) {
                float b0 = bias[n];
                float v = cr[0] + b0;
                out[(size_t)m * ldOut + n] = v > 0.f ? v : 0.f;
                float v2 = cr[2] + b0;
                out[(size_t)(m + 8) * ldOut + n] = v2 > 0.f ? v2 : 0.f;
            }
            if (n + 1 < N) {
                float b1 = bias[n + 1];
                float v = cr[1] + b1;
                out[(size_t)m * ldOut + n + 1] = v > 0.f ? v : 0.f;
                float v2 = cr[3] + b1;
                out[(size_t)(m + 8) * ldOut + n + 1] = v2 > 0.f ? v2 : 0.f;
            }
        }
    }
}

// y[b] = sigmoid( dot(h2[b,:], W_out[0,:]) + b_out ), K = 256, one warp per row
__global__ void head_kernel(const float* __restrict__ h2,
                            const float* __restrict__ W_out,
                            const float* __restrict__ b_out,
                            float* __restrict__ out)
{
    int b = blockIdx.x;
    int lane = threadIdx.x;
    float s = 0.f;
    #pragma unroll
    for (int k = lane; k < 256; k += 32)
        s += h2[b * 256 + k] * W_out[k];
    #pragma unroll
    for (int o = 16; o > 0; o >>= 1)
        s += __shfl_down_sync(0xFFFFFFFFu, s, o);
    if (lane == 0)
        out[b] = 1.0f / (1.0f + expf(-(s + b_out[0])));
}

static constexpr int SMEM_128_ADJ =
    (2 * 128 * AS_STR + 2 * 128 * AS_STR + 2 * 32 * ADJ_STR) * 4;  // 108544 B
static constexpr int SMEM_64_DENSE =
    (2 * 64 * AS_STR + 2 * 64 * AS_STR) * 4;                       // 36864 B

static void launch_masked(const float* A, int ldA, const float* W, int ldW,
                          const float* adj, int ldAdj, const float* bias,
                          float* out, int ldOut, int N, int K)
{
    dim3 grid((N + 127) / 128, 512 / 128);
    gemm_tf32<128, 128, true><<<grid, 256, SMEM_128_ADJ>>>(
        A, ldA, W, ldW, adj, ldAdj, bias, out, ldOut, N, K);
}

static void launch_dense(const float* A, int ldA, const float* W, int ldW,
                         const float* bias, float* out, int ldOut, int N, int K)
{
    dim3 grid((N + 63) / 64, 512 / 64);
    gemm_tf32<64, 64, false><<<grid, 256, SMEM_64_DENSE>>>(
        A, ldA, W, ldW, nullptr, 0, bias, out, ldOut, N, K);
}

extern "C" void kernel_launch(void* const* d_in, const int* in_sizes, int n_in,
                              void* d_out, int out_size)
{
    const float* in_mat  = (const float*)d_in[0];   // [512, 28000]
    const float* adj_sg  = (const float*)d_in[1];   // [20000, 5000]
    const float* adj_gp  = (const float*)d_in[2];   // [5000, 3000]
    const float* adj_br  = (const float*)d_in[3];   // [8000, 3000]
    const float* adj_pp  = (const float*)d_in[4];   // [3000, 3000]
    const float* W_sg    = (const float*)d_in[5];   // [5000, 20000]
    const float* b_sg    = (const float*)d_in[6];
    const float* W_gp    = (const float*)d_in[7];   // [3000, 5000]
    const float* b_gp    = (const float*)d_in[8];
    const float* W_br    = (const float*)d_in[9];   // [3000, 8000]
    const float* b_br    = (const float*)d_in[10];
    const float* W_pp    = (const float*)d_in[11];  // [3000, 3000]
    const float* b_pp    = (const float*)d_in[12];
    const float* W_h1    = (const float*)d_in[13];  // [1024, 6000]
    const float* b_h1    = (const float*)d_in[14];
    const float* W_h2    = (const float*)d_in[15];  // [256, 1024]
    const float* b_h2    = (const float*)d_in[16];
    const float* W_out   = (const float*)d_in[17];  // [1, 256]
    const float* b_out   = (const float*)d_in[18];
    float* out = (float*)d_out;                     // [512, 1]

    static bool attr_set = false;
    if (!attr_set) {
        cudaFuncSetAttribute(gemm_tf32<128, 128, true>,
                             cudaFuncAttributeMaxDynamicSharedMemorySize, SMEM_128_ADJ);
        attr_set = true;
    }

    float *bridge, *fuse, *h1, *h2;
    cudaGetSymbolAddress((void**)&bridge, g_bridge);
    cudaGetSymbolAddress((void**)&fuse,   g_fuse);
    cudaGetSymbolAddress((void**)&h1,     g_h1);
    cudaGetSymbolAddress((void**)&h2,     g_h2);

    // snp layer: cols [8000, 28000) of in_mat  -> bridge[:, 0:5000)
    launch_masked(in_mat + 8000, 28000, W_sg, 20000, adj_sg, 5000, b_sg,
                  bridge, 8000, 5000, 20000);
    // gene layer: cols [3000, 8000) -> bridge[:, 5000:8000)
    launch_masked(in_mat + 3000, 28000, W_gp, 5000, adj_gp, 3000, b_gp,
                  bridge + 5000, 8000, 3000, 5000);
    // protein layer: cols [0, 3000) -> fuse[:, 3000:6000)
    launch_masked(in_mat, 28000, W_pp, 3000, adj_pp, 3000, b_pp,
                  fuse + 3000, 6000, 3000, 3000);
    // bridge layer -> fuse[:, 0:3000)
    launch_masked(bridge, 8000, W_br, 8000, adj_br, 3000, b_br,
                  fuse, 6000, 3000, 8000);
    // dense layers
    launch_dense(fuse, 6000, W_h1, 6000, b_h1, h1, 1024, 1024, 6000);
    launch_dense(h1, 1024, W_h2, 1024, b_h2, h2, 256, 256, 1024);
    // sigmoid head
    head_kernel<<<512, 32>>>(h2, W_out, b_out, out);
}